// round 12
// baseline (speedup 1.0000x reference)
#include <cuda_runtime.h>
#include <cuda_fp16.h>
#include <cstdint>

#define NEG_SLOPE 0.1f
__device__ __forceinline__ float lrelu(float v) { return v >= 0.f ? v : NEG_SLOPE * v; }

// ---------------- static scratch ----------------
#define MAXN 50176
#define MAXE 5000000
__device__ __align__(16) __half g_xc[MAXN * 80];     // [N,80] half: 0..39 agg, 40..79 x
__device__ __align__(16) __half g_w1cat[256 * 80];   // [256,80] = [w_rel|w_root] half
__device__ __align__(16) __half g_wl[3 * 256 * 256]; // w_l1,w_l2,w_l3 half
__device__ __align__(16) __half g_h0[MAXN * 256];
__device__ __align__(16) __half g_h1[MAXN * 256];
__device__ int g_cnt[MAXN];
__device__ int g_off[MAXN + 1];
__device__ int g_cur[MAXN];
__device__ int g_esrc[MAXE];
__device__ int g_bsum[64];
__device__ int g_bbase[64];

// per-block int64-vs-int32 detection for edge_index (values < 2^31 -> odd words all 0)
__device__ __forceinline__ int block_is64(const unsigned* p, long long nwords) {
    int t = threadIdx.x;
    int odd = 0;
    if (t < 256 && (2 * t + 1) < nwords) odd = (p[2 * t + 1] != 0u);
    return !__syncthreads_or(odd);
}

// ================= fused front: count | encoder | pack | out_init =================
__global__ void fused_front(const void* __restrict__ eidx, int E,
                            const float* __restrict__ pose, const float* __restrict__ views,
                            const float* __restrict__ w_e1, const float* __restrict__ b_e1,
                            const float* __restrict__ w_e2, const float* __restrict__ b_e2,
                            const float* __restrict__ w_rel, const float* __restrict__ w_root,
                            const float* __restrict__ w_l1, const float* __restrict__ w_l2,
                            const float* __restrict__ w_l3,
                            const float* __restrict__ b_pred, float* __restrict__ out,
                            int N, int nbCnt, int nbEnc, int nbPack, int nbRnd) {
    int bx = blockIdx.x;
    int t = threadIdx.x;

    if (bx < nbCnt) {
        int is64 = block_is64((const unsigned*)eidx, 2LL * E * 2);
        int base = bx * 1024;
#pragma unroll
        for (int j = 0; j < 4; j++) {
            int e = base + t + j * 256;
            if (e < E) {
                int dst;
                if (is64) dst = (int)((const long long*)eidx)[(size_t)E + e];
                else      dst = ((const int*)eidx)[E + e];
                atomicAdd(&g_cnt[dst], 1);
            }
        }
        return;
    }
    bx -= nbCnt;

    if (bx < nbEnc) {
        __shared__ float sw1[81], sb1[9], sw2[27], sb2;
        if (t < 81) sw1[t] = w_e1[t];
        if (t < 9)  sb1[t] = b_e1[t];
        if (t >= 96 && t < 123) sw2[t - 96] = w_e2[t - 96];
        if (t == 127) sb2 = b_e2[0];
        __syncthreads();

        int n = bx * 256 + t;
        if (n >= N) return;

        __half* xo = g_xc + (size_t)n * 80 + 40;
        xo[0] = __float2half_rn(pose[n * 3 + 0]);
        xo[1] = __float2half_rn(pose[n * 3 + 1]);
        xo[2] = __float2half_rn(pose[n * 3 + 2]);

        const float* vin = views + (size_t)n * 453;

        float cur[9];
        {
            float in[3][3];
#pragma unroll
            for (int ci = 0; ci < 3; ci++)
#pragma unroll
                for (int k = 0; k < 3; k++) in[ci][k] = vin[ci * 151 + k];
#pragma unroll
            for (int c1 = 0; c1 < 9; c1++) {
                float a = sb1[c1];
#pragma unroll
                for (int ci = 0; ci < 3; ci++)
#pragma unroll
                    for (int k = 0; k < 3; k++) a += sw1[c1 * 9 + ci * 3 + k] * in[ci][k];
                cur[c1] = lrelu(a);
            }
        }
        for (int tt = 0; tt < 37; tt++) {
            float b9[9], c9[9];
#pragma unroll
            for (int which = 0; which < 2; which++) {
                int pos = 2 * tt + 1 + which;
                float in[3][3];
#pragma unroll
                for (int ci = 0; ci < 3; ci++)
#pragma unroll
                    for (int k = 0; k < 3; k++) in[ci][k] = vin[ci * 151 + 2 * pos + k];
                float* dst = which == 0 ? b9 : c9;
#pragma unroll
                for (int c1 = 0; c1 < 9; c1++) {
                    float a = sb1[c1];
#pragma unroll
                    for (int ci = 0; ci < 3; ci++)
#pragma unroll
                        for (int k = 0; k < 3; k++) a += sw1[c1 * 9 + ci * 3 + k] * in[ci][k];
                    dst[c1] = lrelu(a);
                }
            }
            float acc = sb2;
#pragma unroll
            for (int c1 = 0; c1 < 9; c1++)
                acc += cur[c1] * sw2[c1 * 3 + 0] + b9[c1] * sw2[c1 * 3 + 1] + c9[c1] * sw2[c1 * 3 + 2];
            xo[3 + tt] = __float2half_rn(lrelu(acc));
#pragma unroll
            for (int c1 = 0; c1 < 9; c1++) cur[c1] = c9[c1];
        }
        return;
    }
    bx -= nbEnc;

    if (bx < nbPack) {
        int i = bx * 256 + t;
        if (i < 256 * 80) {
            int n = i / 80, j = i % 80;
            g_w1cat[i] = __float2half_rn((j < 40) ? w_rel[n * 40 + j] : w_root[n * 40 + j - 40]);
        }
        return;
    }
    bx -= nbPack;

    if (bx < nbRnd) {
        int i = bx * 256 + t;
        if (i < 3 * 65536) {
            int which = i >> 16;
            const float* w = which == 0 ? w_l1 : (which == 1 ? w_l2 : w_l3);
            g_wl[i] = __float2half_rn(w[i & 65535]);
        }
        return;
    }
    bx -= nbRnd;

    {
        int i = bx * 256 + t;
        if (i < N) out[i] = b_pred[0];
    }
}

// ================= scan (3 kernels) =================
__device__ __forceinline__ int block_incl_scan(int v) {
    __shared__ int ws[32];
    int lane = threadIdx.x & 31, wid = threadIdx.x >> 5;
    int x = v;
#pragma unroll
    for (int o = 1; o < 32; o <<= 1) {
        int y = __shfl_up_sync(0xffffffffu, x, o);
        if (lane >= o) x += y;
    }
    if (lane == 31) ws[wid] = x;
    __syncthreads();
    if (wid == 0) {
        int s = ws[lane];
#pragma unroll
        for (int o = 1; o < 32; o <<= 1) {
            int y = __shfl_up_sync(0xffffffffu, s, o);
            if (lane >= o) s += y;
        }
        ws[lane] = s;
    }
    __syncthreads();
    int base = (wid > 0) ? ws[wid - 1] : 0;
    return base + x;
}

__global__ void scan_a(int N) {
    int i = blockIdx.x * 1024 + threadIdx.x;
    int v = (i < N) ? g_cnt[i] : 0;
    int incl = block_incl_scan(v);
    if (threadIdx.x == 1023) g_bsum[blockIdx.x] = incl;
}
__global__ void scan_b(int nblk) {
    int t = threadIdx.x;
    int v = (t < nblk) ? g_bsum[t] : 0;
    int incl = block_incl_scan(v);
    if (t < nblk) g_bbase[t] = incl - v;
}
__global__ void scan_c(int N) {
    int b = blockIdx.x;
    int i = b * 1024 + threadIdx.x;
    int v = (i < N) ? g_cnt[i] : 0;
    int incl = block_incl_scan(v);
    int excl = g_bbase[b] + incl - v;
    if (i < N) { g_off[i] = excl; g_cur[i] = excl; }
    if (i == N - 1) g_off[N] = excl + v;
}

// ================= fill =================
__global__ void fill_kernel(const void* __restrict__ eidx, int E) {
    int is64 = block_is64((const unsigned*)eidx, 2LL * E * 2);
    int base = blockIdx.x * 1024;
    int t = threadIdx.x;
#pragma unroll
    for (int j = 0; j < 4; j++) {
        int e = base + t + j * 256;
        if (e < E) {
            int src, dst;
            if (is64) {
                const long long* p = (const long long*)eidx;
                src = (int)p[e];
                dst = (int)p[(size_t)E + e];
            } else {
                const int* p = (const int*)eidx;
                src = p[e];
                dst = p[E + e];
            }
            int pos = atomicAdd(&g_cur[dst], 1);
            g_esrc[pos] = src;
        }
    }
}

// ===== gather: agg[n] = sum x[src]; 5 threads/node, one 16B block (8 halves) each =====
__global__ void gather_kernel(int N) {
    int idx = blockIdx.x * blockDim.x + threadIdx.x;
    int node = idx / 5;
    int part = idx - node * 5;
    if (node >= N) return;
    int beg = g_off[node], end = g_off[node + 1];

    float acc[8];
#pragma unroll
    for (int i = 0; i < 8; i++) acc[i] = 0.f;

    const __half* xbase = g_xc + 40 + part * 8;

    int e = beg;
    for (; e + 3 < end; e += 4) {
        int s0 = g_esrc[e], s1 = g_esrc[e + 1], s2 = g_esrc[e + 2], s3 = g_esrc[e + 3];
        uint4 v0 = *(const uint4*)(xbase + (size_t)s0 * 80);
        uint4 v1 = *(const uint4*)(xbase + (size_t)s1 * 80);
        uint4 v2 = *(const uint4*)(xbase + (size_t)s2 * 80);
        uint4 v3 = *(const uint4*)(xbase + (size_t)s3 * 80);
        const uint4* vs[4] = {&v0, &v1, &v2, &v3};
#pragma unroll
        for (int u = 0; u < 4; u++) {
            const __half2* h = (const __half2*)vs[u];
#pragma unroll
            for (int q = 0; q < 4; q++) {
                float2 f = __half22float2(h[q]);
                acc[2 * q + 0] += f.x;
                acc[2 * q + 1] += f.y;
            }
        }
    }
    for (; e < end; e++) {
        int s0 = g_esrc[e];
        uint4 v = *(const uint4*)(xbase + (size_t)s0 * 80);
        const __half2* h = (const __half2*)&v;
#pragma unroll
        for (int q = 0; q < 4; q++) {
            float2 f = __half22float2(h[q]);
            acc[2 * q + 0] += f.x;
            acc[2 * q + 1] += f.y;
        }
    }
    uint4 o;
    __half2* oh = (__half2*)&o;
#pragma unroll
    for (int q = 0; q < 4; q++) oh[q] = __floats2half2_rn(acc[2 * q], acc[2 * q + 1]);
    *(uint4*)(g_xc + (size_t)node * 80 + part * 8) = o;
}

// ================= fp16 GEMM with ldmatrix =================
// mma.m16n8k16.f16 f32-accum; block tile 128x128, warp tile 64x32, K-chunk 64,
// 3-stage cp.async, XOR-swizzled smem (word addr = row*32 + (c ^ ((row&7)<<2))).
// Fragments loaded via ldmatrix.x4 (A) / ldmatrix.x2 (B): 8 instrs/step vs 24 LDS.
__device__ __forceinline__ void mma_f16(float c[4], const uint32_t a[4], const uint32_t b[2]) {
    asm volatile(
        "mma.sync.aligned.m16n8k16.row.col.f32.f16.f16.f32 "
        "{%0,%1,%2,%3}, {%4,%5,%6,%7}, {%8,%9}, {%0,%1,%2,%3};\n"
        : "+f"(c[0]), "+f"(c[1]), "+f"(c[2]), "+f"(c[3])
        : "r"(a[0]), "r"(a[1]), "r"(a[2]), "r"(a[3]), "r"(b[0]), "r"(b[1]));
}
__device__ __forceinline__ void ldsm_x4(uint32_t& r0, uint32_t& r1, uint32_t& r2, uint32_t& r3,
                                        uint32_t addr) {
    asm volatile("ldmatrix.sync.aligned.m8n8.x4.shared.b16 {%0,%1,%2,%3}, [%4];"
                 : "=r"(r0), "=r"(r1), "=r"(r2), "=r"(r3) : "r"(addr));
}
__device__ __forceinline__ void ldsm_x2(uint32_t& r0, uint32_t& r1, uint32_t addr) {
    asm volatile("ldmatrix.sync.aligned.m8n8.x2.shared.b16 {%0,%1}, [%2];"
                 : "=r"(r0), "=r"(r1) : "r"(addr));
}
__device__ __forceinline__ void cpasync16(uint32_t saddr, const void* g, int sz) {
    asm volatile("cp.async.cg.shared.global [%0], [%1], 16, %2;"
                 :: "r"(saddr), "l"(g), "r"(sz));
}

#define STAGE_WORDS 8192  // A: 128x32 words (half2), B same at +4096
#define NSTAGE 3

template <int FUSE_PRED>
__global__ __launch_bounds__(256, 2)
void gemm_f16(const __half* __restrict__ A, const __half* __restrict__ B,
              const float* __restrict__ bias, __half* __restrict__ C, int M, int K,
              const float* __restrict__ w_pred, float* __restrict__ out) {
    extern __shared__ uint32_t sm[];
    uint32_t sbase = (uint32_t)__cvta_generic_to_shared(sm);

    int tid = threadIdx.x;
    int mB = blockIdx.x * 128;
    int nB = blockIdx.y * 128;
    int wid = tid >> 5, lane = tid & 31;
    int wm = wid >> 2, wn = wid & 3;
    int g = lane >> 2, t = lane & 3;

    // ldmatrix per-lane addressing constants
    int lr = lane & 7;                 // row-within-8 (m&7 == n&7 == lr for addressed rows)
    int xlr = lr << 2;                 // swizzle XOR constant (word units)
    int arow = lr + ((lane >> 3) & 1) * 8;  // A: row offset within 16-row tile
    int acol = (lane >> 4) * 4;             // A: +4 words for k8-15 tiles
    int bcol = ((lane >> 3) & 1) * 4;       // B: +4 words for second 8x8 (lanes 8-15)

    const int nk = (K + 63) / 64;

    float c[4][4][4];
#pragma unroll
    for (int i = 0; i < 4; i++)
#pragma unroll
        for (int j = 0; j < 4; j++)
#pragma unroll
            for (int r = 0; r < 4; r++) c[i][j][r] = 0.f;

    auto load_chunk = [&](int k0, int stage) {
#pragma unroll
        for (int p = 0; p < 4; p++) {
            int lin = tid + p * 256;
            int r = lin >> 3, cq = lin & 7;
            int k = k0 + cq * 8;
            bool kv = (k < K);
            int swc = (cq * 4) ^ ((r & 7) << 2);
            uint32_t so = sbase + ((stage * STAGE_WORDS + r * 32 + swc) << 2);
            {
                int m = mB + r;
                bool v = kv && (m < M);
                cpasync16(so, v ? (const void*)(A + (size_t)m * K + k) : (const void*)A,
                          v ? 16 : 0);
            }
            {
                int n = nB + r;
                cpasync16(so + (4096 << 2),
                          kv ? (const void*)(B + (size_t)n * K + k) : (const void*)B,
                          kv ? 16 : 0);
            }
        }
        asm volatile("cp.async.commit_group;");
    };

    load_chunk(0, 0);
    if (nk > 1) load_chunk(64, 1);

    for (int i = 0; i < nk; i++) {
        if (i + 2 < nk) {
            load_chunk((i + 2) * 64, (i + 2) % NSTAGE);
            asm volatile("cp.async.wait_group 2;");
        } else if (i + 1 < nk) {
            asm volatile("cp.async.wait_group 1;");
        } else {
            asm volatile("cp.async.wait_group 0;");
        }
        __syncthreads();

        uint32_t As_b = sbase + ((i % NSTAGE) * STAGE_WORDS << 2);
        uint32_t Bs_b = As_b + (4096 << 2);
#pragma unroll
        for (int kk2 = 0; kk2 < 32; kk2 += 8) {  // 4 x k16 steps (word cols)
            uint32_t a[4][4], b[4][2];
#pragma unroll
            for (int mt = 0; mt < 4; mt++) {
                int m = wm * 64 + mt * 16 + arow;
                uint32_t ad = As_b + ((m * 32 + ((kk2 + acol) ^ xlr)) << 2);
                ldsm_x4(a[mt][0], a[mt][1], a[mt][2], a[mt][3], ad);
            }
#pragma unroll
            for (int nt = 0; nt < 4; nt++) {
                int n = wn * 32 + nt * 8 + lr;
                uint32_t bd = Bs_b + ((n * 32 + ((kk2 + bcol) ^ xlr)) << 2);
                ldsm_x2(b[nt][0], b[nt][1], bd);
            }
#pragma unroll
            for (int mt = 0; mt < 4; mt++)
#pragma unroll
                for (int nt = 0; nt < 4; nt++) mma_f16(c[mt][nt], a[mt], b[nt]);
        }
        __syncthreads();
    }

#pragma unroll
    for (int mt = 0; mt < 4; mt++) {
        int m0 = mB + wm * 64 + mt * 16 + g;
        float d0 = 0.f, d1 = 0.f;
#pragma unroll
        for (int nt = 0; nt < 4; nt++) {
            int n0 = nB + wn * 32 + nt * 8 + 2 * t;
            float bx = bias[n0], by = bias[n0 + 1];
            float v0x = lrelu(c[mt][nt][0] + bx);
            float v0y = lrelu(c[mt][nt][1] + by);
            float v1x = lrelu(c[mt][nt][2] + bx);
            float v1y = lrelu(c[mt][nt][3] + by);
            if (FUSE_PRED) {
                float wx = w_pred[n0], wy = w_pred[n0 + 1];
                d0 += v0x * wx + v0y * wy;
                d1 += v1x * wx + v1y * wy;
            } else {
                if (m0 < M)
                    *(__half2*)(C + (size_t)m0 * 256 + n0) = __floats2half2_rn(v0x, v0y);
                if (m0 + 8 < M)
                    *(__half2*)(C + (size_t)(m0 + 8) * 256 + n0) = __floats2half2_rn(v1x, v1y);
            }
        }
        if (FUSE_PRED) {
            d0 += __shfl_xor_sync(0xffffffffu, d0, 1);
            d0 += __shfl_xor_sync(0xffffffffu, d0, 2);
            d1 += __shfl_xor_sync(0xffffffffu, d1, 1);
            d1 += __shfl_xor_sync(0xffffffffu, d1, 2);
            if (t == 0) {
                if (m0 < M)     atomicAdd(out + m0, d0);
                if (m0 + 8 < M) atomicAdd(out + m0 + 8, d1);
            }
        }
    }
}

extern "C" void kernel_launch(void* const* d_in, const int* in_sizes, int n_in,
                              void* d_out, int out_size) {
    const float* pose   = (const float*)d_in[0];
    const float* views  = (const float*)d_in[1];
    const void*  eidx   = d_in[2];
    const float* w_e1   = (const float*)d_in[3];
    const float* b_e1   = (const float*)d_in[4];
    const float* w_e2   = (const float*)d_in[5];
    const float* b_e2   = (const float*)d_in[6];
    const float* w_rel  = (const float*)d_in[7];
    const float* b_rel  = (const float*)d_in[8];
    const float* w_root = (const float*)d_in[9];
    const float* w_l1   = (const float*)d_in[10];
    const float* b_l1   = (const float*)d_in[11];
    const float* w_l2   = (const float*)d_in[12];
    const float* b_l2   = (const float*)d_in[13];
    const float* w_l3   = (const float*)d_in[14];
    const float* b_l3   = (const float*)d_in[15];
    const float* w_pred = (const float*)d_in[16];
    const float* b_pred = (const float*)d_in[17];
    float* out = (float*)d_out;

    int N = in_sizes[0] / 3;
    int E = in_sizes[2] / 2;

    __half *xc, *w1, *wl, *h0, *h1;
    cudaGetSymbolAddress((void**)&xc, g_xc);
    cudaGetSymbolAddress((void**)&w1, g_w1cat);
    cudaGetSymbolAddress((void**)&wl, g_wl);
    cudaGetSymbolAddress((void**)&h0, g_h0);
    cudaGetSymbolAddress((void**)&h1, g_h1);
    int* cnt;
    cudaGetSymbolAddress((void**)&cnt, g_cnt);

    const int SMEM = NSTAGE * STAGE_WORDS * 4;  // 98304 B
    cudaFuncSetAttribute(gemm_f16<0>, cudaFuncAttributeMaxDynamicSharedMemorySize, SMEM);
    cudaFuncSetAttribute(gemm_f16<1>, cudaFuncAttributeMaxDynamicSharedMemorySize, SMEM);

    cudaMemsetAsync(cnt, 0, (size_t)N * sizeof(int));

    int nbCnt = (E + 1023) / 1024;
    int nbEnc = (N + 255) / 256;
    int nbPack = (256 * 80 + 255) / 256;
    int nbRnd = (3 * 65536 + 255) / 256;
    int nbOut = (N + 255) / 256;
    fused_front<<<nbCnt + nbEnc + nbPack + nbRnd + nbOut, 256>>>(
        eidx, E, pose, views, w_e1, b_e1, w_e2, b_e2,
        w_rel, w_root, w_l1, w_l2, w_l3, b_pred, out,
        N, nbCnt, nbEnc, nbPack, nbRnd);

    int nblk = (N + 1023) / 1024;
    scan_a<<<nblk, 1024>>>(N);
    scan_b<<<1, 1024>>>(nblk);
    scan_c<<<nblk, 1024>>>(N);

    fill_kernel<<<(E + 1023) / 1024, 256>>>(eidx, E);
    gather_kernel<<<(5 * N + 255) / 256, 256>>>(N);

    dim3 ggrid((N + 127) / 128, 2);
    gemm_f16<0><<<ggrid, 256, SMEM>>>(xc, w1, b_rel, h0, N, 80, nullptr, nullptr);
    gemm_f16<0><<<ggrid, 256, SMEM>>>(h0, wl, b_l1, h1, N, 256, nullptr, nullptr);
    gemm_f16<0><<<ggrid, 256, SMEM>>>(h1, wl + 65536, b_l2, h0, N, 256, nullptr, nullptr);
    gemm_f16<1><<<ggrid, 256, SMEM>>>(h0, wl + 2 * 65536, b_l3, nullptr, N, 256, w_pred, out);
}

// round 13
// speedup vs baseline: 1.3017x; 1.3017x over previous
#include <cuda_runtime.h>
#include <cuda_fp16.h>
#include <cstdint>

#define NEG_SLOPE 0.1f
__device__ __forceinline__ float lrelu(float v) { return v >= 0.f ? v : NEG_SLOPE * v; }

// ---------------- static scratch ----------------
#define MAXN 50176
#define MAXE 5000000
__device__ __align__(16) __half g_xc[MAXN * 80];     // [N,80] half: 0..39 agg, 40..79 x
__device__ __align__(16) __half g_w1cat[256 * 80];   // [256,80] = [w_rel|w_root] half
__device__ __align__(16) __half g_wl[3 * 256 * 256]; // w_l1,w_l2,w_l3 half
__device__ __align__(16) __half g_h0[MAXN * 256];
__device__ __align__(16) __half g_h1[MAXN * 256];
__device__ int g_cnt[MAXN];
__device__ int g_off[MAXN + 1];
__device__ int g_cur[MAXN];
__device__ int g_esrc[MAXE];
__device__ int g_bsum[64];
__device__ int g_bbase[64];

// per-block int64-vs-int32 detection for edge_index (values < 2^31 -> odd words all 0)
__device__ __forceinline__ int block_is64(const unsigned* p, long long nwords) {
    int t = threadIdx.x;
    int odd = 0;
    if (t < 256 && (2 * t + 1) < nwords) odd = (p[2 * t + 1] != 0u);
    return !__syncthreads_or(odd);
}

// ================= fused front: count | encoder | pack | out_init =================
__global__ void fused_front(const void* __restrict__ eidx, int E,
                            const float* __restrict__ pose, const float* __restrict__ views,
                            const float* __restrict__ w_e1, const float* __restrict__ b_e1,
                            const float* __restrict__ w_e2, const float* __restrict__ b_e2,
                            const float* __restrict__ w_rel, const float* __restrict__ w_root,
                            const float* __restrict__ w_l1, const float* __restrict__ w_l2,
                            const float* __restrict__ w_l3,
                            const float* __restrict__ b_pred, float* __restrict__ out,
                            int N, int nbCnt, int nbEnc, int nbPack, int nbRnd) {
    int bx = blockIdx.x;
    int t = threadIdx.x;

    if (bx < nbCnt) {
        int is64 = block_is64((const unsigned*)eidx, 2LL * E * 2);
        int base = bx * 1024;
#pragma unroll
        for (int j = 0; j < 4; j++) {
            int e = base + t + j * 256;
            if (e < E) {
                int dst;
                if (is64) dst = (int)((const long long*)eidx)[(size_t)E + e];
                else      dst = ((const int*)eidx)[E + e];
                atomicAdd(&g_cnt[dst], 1);
            }
        }
        return;
    }
    bx -= nbCnt;

    if (bx < nbEnc) {
        __shared__ float sw1[81], sb1[9], sw2[27], sb2;
        if (t < 81) sw1[t] = w_e1[t];
        if (t < 9)  sb1[t] = b_e1[t];
        if (t >= 96 && t < 123) sw2[t - 96] = w_e2[t - 96];
        if (t == 127) sb2 = b_e2[0];
        __syncthreads();

        int n = bx * 256 + t;
        if (n >= N) return;

        __half* xo = g_xc + (size_t)n * 80 + 40;
        xo[0] = __float2half_rn(pose[n * 3 + 0]);
        xo[1] = __float2half_rn(pose[n * 3 + 1]);
        xo[2] = __float2half_rn(pose[n * 3 + 2]);

        const float* vin = views + (size_t)n * 453;

        float cur[9];
        {
            float in[3][3];
#pragma unroll
            for (int ci = 0; ci < 3; ci++)
#pragma unroll
                for (int k = 0; k < 3; k++) in[ci][k] = vin[ci * 151 + k];
#pragma unroll
            for (int c1 = 0; c1 < 9; c1++) {
                float a = sb1[c1];
#pragma unroll
                for (int ci = 0; ci < 3; ci++)
#pragma unroll
                    for (int k = 0; k < 3; k++) a += sw1[c1 * 9 + ci * 3 + k] * in[ci][k];
                cur[c1] = lrelu(a);
            }
        }
        for (int tt = 0; tt < 37; tt++) {
            float b9[9], c9[9];
#pragma unroll
            for (int which = 0; which < 2; which++) {
                int pos = 2 * tt + 1 + which;
                float in[3][3];
#pragma unroll
                for (int ci = 0; ci < 3; ci++)
#pragma unroll
                    for (int k = 0; k < 3; k++) in[ci][k] = vin[ci * 151 + 2 * pos + k];
                float* dst = which == 0 ? b9 : c9;
#pragma unroll
                for (int c1 = 0; c1 < 9; c1++) {
                    float a = sb1[c1];
#pragma unroll
                    for (int ci = 0; ci < 3; ci++)
#pragma unroll
                        for (int k = 0; k < 3; k++) a += sw1[c1 * 9 + ci * 3 + k] * in[ci][k];
                    dst[c1] = lrelu(a);
                }
            }
            float acc = sb2;
#pragma unroll
            for (int c1 = 0; c1 < 9; c1++)
                acc += cur[c1] * sw2[c1 * 3 + 0] + b9[c1] * sw2[c1 * 3 + 1] + c9[c1] * sw2[c1 * 3 + 2];
            xo[3 + tt] = __float2half_rn(lrelu(acc));
#pragma unroll
            for (int c1 = 0; c1 < 9; c1++) cur[c1] = c9[c1];
        }
        return;
    }
    bx -= nbEnc;

    if (bx < nbPack) {
        int i = bx * 256 + t;
        if (i < 256 * 80) {
            int n = i / 80, j = i % 80;
            g_w1cat[i] = __float2half_rn((j < 40) ? w_rel[n * 40 + j] : w_root[n * 40 + j - 40]);
        }
        return;
    }
    bx -= nbPack;

    if (bx < nbRnd) {
        int i = bx * 256 + t;
        if (i < 3 * 65536) {
            int which = i >> 16;
            const float* w = which == 0 ? w_l1 : (which == 1 ? w_l2 : w_l3);
            g_wl[i] = __float2half_rn(w[i & 65535]);
        }
        return;
    }
    bx -= nbRnd;

    {
        int i = bx * 256 + t;
        if (i < N) out[i] = b_pred[0];
    }
}

// ================= scan (3 kernels) =================
__device__ __forceinline__ int block_incl_scan(int v) {
    __shared__ int ws[32];
    int lane = threadIdx.x & 31, wid = threadIdx.x >> 5;
    int x = v;
#pragma unroll
    for (int o = 1; o < 32; o <<= 1) {
        int y = __shfl_up_sync(0xffffffffu, x, o);
        if (lane >= o) x += y;
    }
    if (lane == 31) ws[wid] = x;
    __syncthreads();
    if (wid == 0) {
        int s = ws[lane];
#pragma unroll
        for (int o = 1; o < 32; o <<= 1) {
            int y = __shfl_up_sync(0xffffffffu, s, o);
            if (lane >= o) s += y;
        }
        ws[lane] = s;
    }
    __syncthreads();
    int base = (wid > 0) ? ws[wid - 1] : 0;
    return base + x;
}

__global__ void scan_a(int N) {
    int i = blockIdx.x * 1024 + threadIdx.x;
    int v = (i < N) ? g_cnt[i] : 0;
    int incl = block_incl_scan(v);
    if (threadIdx.x == 1023) g_bsum[blockIdx.x] = incl;
}
__global__ void scan_b(int nblk) {
    int t = threadIdx.x;
    int v = (t < nblk) ? g_bsum[t] : 0;
    int incl = block_incl_scan(v);
    if (t < nblk) g_bbase[t] = incl - v;
}
__global__ void scan_c(int N) {
    int b = blockIdx.x;
    int i = b * 1024 + threadIdx.x;
    int v = (i < N) ? g_cnt[i] : 0;
    int incl = block_incl_scan(v);
    int excl = g_bbase[b] + incl - v;
    if (i < N) { g_off[i] = excl; g_cur[i] = excl; }
    if (i == N - 1) g_off[N] = excl + v;
}

// ================= fill =================
__global__ void fill_kernel(const void* __restrict__ eidx, int E) {
    int is64 = block_is64((const unsigned*)eidx, 2LL * E * 2);
    int base = blockIdx.x * 1024;
    int t = threadIdx.x;
#pragma unroll
    for (int j = 0; j < 4; j++) {
        int e = base + t + j * 256;
        if (e < E) {
            int src, dst;
            if (is64) {
                const long long* p = (const long long*)eidx;
                src = (int)p[e];
                dst = (int)p[(size_t)E + e];
            } else {
                const int* p = (const int*)eidx;
                src = p[e];
                dst = p[E + e];
            }
            int pos = atomicAdd(&g_cur[dst], 1);
            g_esrc[pos] = src;
        }
    }
}

// ===== gather: warp per node; lanes 0..19 each own one half2 column of x-row =====
// Per edge the warp reads the 80B source x-row coalesced; fp32 accumulation.
__global__ void gather_kernel(int N) {
    int w = (blockIdx.x * blockDim.x + threadIdx.x) >> 5;
    int lane = threadIdx.x & 31;
    if (w >= N || lane >= 20) return;
    int beg = g_off[w], end = g_off[w + 1];

    float ax = 0.f, ay = 0.f;
    const __half2* xb = (const __half2*)g_xc;  // row s: half2 index s*40 + 20 + lane

    int e = beg;
    for (; e + 3 < end; e += 4) {
        int s0 = g_esrc[e], s1 = g_esrc[e + 1], s2 = g_esrc[e + 2], s3 = g_esrc[e + 3];
        __half2 v0 = xb[(size_t)s0 * 40 + 20 + lane];
        __half2 v1 = xb[(size_t)s1 * 40 + 20 + lane];
        __half2 v2 = xb[(size_t)s2 * 40 + 20 + lane];
        __half2 v3 = xb[(size_t)s3 * 40 + 20 + lane];
        float2 f0 = __half22float2(v0);
        float2 f1 = __half22float2(v1);
        float2 f2 = __half22float2(v2);
        float2 f3 = __half22float2(v3);
        ax += (f0.x + f1.x) + (f2.x + f3.x);
        ay += (f0.y + f1.y) + (f2.y + f3.y);
    }
    for (; e < end; e++) {
        float2 f = __half22float2(xb[(size_t)g_esrc[e] * 40 + 20 + lane]);
        ax += f.x;
        ay += f.y;
    }
    ((__half2*)(g_xc + (size_t)w * 80))[lane] = __floats2half2_rn(ax, ay);
}

// ================= fp16 GEMM: C[M,256] = act(A[M,K] @ B[256,K]^T + bias) =============
// mma.m16n8k16.f16.f32-accum; block tile 128x128, warp tile 64x32, K-chunk 64,
// 3-stage cp.async, XOR-swizzled smem (word addr = row*32 + (c ^ ((row&7)<<2))).
__device__ __forceinline__ void mma_f16(float c[4], const uint32_t a[4], const uint32_t b[2]) {
    asm volatile(
        "mma.sync.aligned.m16n8k16.row.col.f32.f16.f16.f32 "
        "{%0,%1,%2,%3}, {%4,%5,%6,%7}, {%8,%9}, {%0,%1,%2,%3};\n"
        : "+f"(c[0]), "+f"(c[1]), "+f"(c[2]), "+f"(c[3])
        : "r"(a[0]), "r"(a[1]), "r"(a[2]), "r"(a[3]), "r"(b[0]), "r"(b[1]));
}
__device__ __forceinline__ void cpasync16(uint32_t saddr, const void* g, int sz) {
    asm volatile("cp.async.cg.shared.global [%0], [%1], 16, %2;"
                 :: "r"(saddr), "l"(g), "r"(sz));
}

#define STAGE_WORDS 8192  // A: 128x32 words (half2), B same at +4096
#define NSTAGE 3

template <int FUSE_PRED>
__global__ __launch_bounds__(256, 2)
void gemm_f16(const __half* __restrict__ A, const __half* __restrict__ B,
              const float* __restrict__ bias, __half* __restrict__ C, int M, int K,
              const float* __restrict__ w_pred, float* __restrict__ out) {
    extern __shared__ uint32_t sm[];
    uint32_t sbase = (uint32_t)__cvta_generic_to_shared(sm);

    int tid = threadIdx.x;
    int mB = blockIdx.x * 128;
    int nB = blockIdx.y * 128;
    int wid = tid >> 5, lane = tid & 31;
    int wm = wid >> 2, wn = wid & 3;
    int g = lane >> 2, t = lane & 3;
    int xg = g << 2;

    const int nk = (K + 63) / 64;

    float c[4][4][4];
#pragma unroll
    for (int i = 0; i < 4; i++)
#pragma unroll
        for (int j = 0; j < 4; j++)
#pragma unroll
            for (int r = 0; r < 4; r++) c[i][j][r] = 0.f;

    // chunk = 64 K-halves = 8 blocks of 16B per row; 128 rows x 8 blocks / 256 thr = 4 iters
    auto load_chunk = [&](int k0, int stage) {
#pragma unroll
        for (int p = 0; p < 4; p++) {
            int lin = tid + p * 256;
            int r = lin >> 3, cq = lin & 7;
            int k = k0 + cq * 8;
            bool kv = (k < K);
            int swc = (cq * 4) ^ ((r & 7) << 2);
            uint32_t so = sbase + ((stage * STAGE_WORDS + r * 32 + swc) << 2);
            {
                int m = mB + r;
                bool v = kv && (m < M);
                cpasync16(so, v ? (const void*)(A + (size_t)m * K + k) : (const void*)A,
                          v ? 16 : 0);
            }
            {
                int n = nB + r;
                cpasync16(so + (4096 << 2),
                          kv ? (const void*)(B + (size_t)n * K + k) : (const void*)B,
                          kv ? 16 : 0);
            }
        }
        asm volatile("cp.async.commit_group;");
    };

    load_chunk(0, 0);
    if (nk > 1) load_chunk(64, 1);

    for (int i = 0; i < nk; i++) {
        if (i + 2 < nk) {
            load_chunk((i + 2) * 64, (i + 2) % NSTAGE);
            asm volatile("cp.async.wait_group 2;");
        } else if (i + 1 < nk) {
            asm volatile("cp.async.wait_group 1;");
        } else {
            asm volatile("cp.async.wait_group 0;");
        }
        __syncthreads();

        const uint32_t* As = sm + (i % NSTAGE) * STAGE_WORDS;
        const uint32_t* Bs = As + 4096;
#pragma unroll
        for (int kk2 = 0; kk2 < 32; kk2 += 8) {  // 4 x k16 steps (word cols)
            int c0 = (kk2 + t) ^ xg;
            int c1 = (kk2 + t + 4) ^ xg;
            uint32_t a[4][4], b[4][2];
#pragma unroll
            for (int mt = 0; mt < 4; mt++) {
                int m = wm * 64 + mt * 16 + g;
                a[mt][0] = As[m * 32 + c0];
                a[mt][1] = As[(m + 8) * 32 + c0];
                a[mt][2] = As[m * 32 + c1];
                a[mt][3] = As[(m + 8) * 32 + c1];
            }
#pragma unroll
            for (int nt = 0; nt < 4; nt++) {
                int n = wn * 32 + nt * 8 + g;
                b[nt][0] = Bs[n * 32 + c0];
                b[nt][1] = Bs[n * 32 + c1];
            }
#pragma unroll
            for (int mt = 0; mt < 4; mt++)
#pragma unroll
                for (int nt = 0; nt < 4; nt++) mma_f16(c[mt][nt], a[mt], b[nt]);
        }
        __syncthreads();
    }

#pragma unroll
    for (int mt = 0; mt < 4; mt++) {
        int m0 = mB + wm * 64 + mt * 16 + g;
        float d0 = 0.f, d1 = 0.f;
#pragma unroll
        for (int nt = 0; nt < 4; nt++) {
            int n0 = nB + wn * 32 + nt * 8 + 2 * t;
            float bx = bias[n0], by = bias[n0 + 1];
            float v0x = lrelu(c[mt][nt][0] + bx);
            float v0y = lrelu(c[mt][nt][1] + by);
            float v1x = lrelu(c[mt][nt][2] + bx);
            float v1y = lrelu(c[mt][nt][3] + by);
            if (FUSE_PRED) {
                float wx = w_pred[n0], wy = w_pred[n0 + 1];
                d0 += v0x * wx + v0y * wy;
                d1 += v1x * wx + v1y * wy;
            } else {
                if (m0 < M)
                    *(__half2*)(C + (size_t)m0 * 256 + n0) = __floats2half2_rn(v0x, v0y);
                if (m0 + 8 < M)
                    *(__half2*)(C + (size_t)(m0 + 8) * 256 + n0) = __floats2half2_rn(v1x, v1y);
            }
        }
        if (FUSE_PRED) {
            d0 += __shfl_xor_sync(0xffffffffu, d0, 1);
            d0 += __shfl_xor_sync(0xffffffffu, d0, 2);
            d1 += __shfl_xor_sync(0xffffffffu, d1, 1);
            d1 += __shfl_xor_sync(0xffffffffu, d1, 2);
            if (t == 0) {
                if (m0 < M)     atomicAdd(out + m0, d0);
                if (m0 + 8 < M) atomicAdd(out + m0 + 8, d1);
            }
        }
    }
}

extern "C" void kernel_launch(void* const* d_in, const int* in_sizes, int n_in,
                              void* d_out, int out_size) {
    const float* pose   = (const float*)d_in[0];
    const float* views  = (const float*)d_in[1];
    const void*  eidx   = d_in[2];
    const float* w_e1   = (const float*)d_in[3];
    const float* b_e1   = (const float*)d_in[4];
    const float* w_e2   = (const float*)d_in[5];
    const float* b_e2   = (const float*)d_in[6];
    const float* w_rel  = (const float*)d_in[7];
    const float* b_rel  = (const float*)d_in[8];
    const float* w_root = (const float*)d_in[9];
    const float* w_l1   = (const float*)d_in[10];
    const float* b_l1   = (const float*)d_in[11];
    const float* w_l2   = (const float*)d_in[12];
    const float* b_l2   = (const float*)d_in[13];
    const float* w_l3   = (const float*)d_in[14];
    const float* b_l3   = (const float*)d_in[15];
    const float* w_pred = (const float*)d_in[16];
    const float* b_pred = (const float*)d_in[17];
    float* out = (float*)d_out;

    int N = in_sizes[0] / 3;
    int E = in_sizes[2] / 2;

    __half *xc, *w1, *wl, *h0, *h1;
    cudaGetSymbolAddress((void**)&xc, g_xc);
    cudaGetSymbolAddress((void**)&w1, g_w1cat);
    cudaGetSymbolAddress((void**)&wl, g_wl);
    cudaGetSymbolAddress((void**)&h0, g_h0);
    cudaGetSymbolAddress((void**)&h1, g_h1);
    int* cnt;
    cudaGetSymbolAddress((void**)&cnt, g_cnt);

    const int SMEM = NSTAGE * STAGE_WORDS * 4;  // 98304 B
    cudaFuncSetAttribute(gemm_f16<0>, cudaFuncAttributeMaxDynamicSharedMemorySize, SMEM);
    cudaFuncSetAttribute(gemm_f16<1>, cudaFuncAttributeMaxDynamicSharedMemorySize, SMEM);

    cudaMemsetAsync(cnt, 0, (size_t)N * sizeof(int));

    int nbCnt = (E + 1023) / 1024;
    int nbEnc = (N + 255) / 256;
    int nbPack = (256 * 80 + 255) / 256;
    int nbRnd = (3 * 65536 + 255) / 256;
    int nbOut = (N + 255) / 256;
    fused_front<<<nbCnt + nbEnc + nbPack + nbRnd + nbOut, 256>>>(
        eidx, E, pose, views, w_e1, b_e1, w_e2, b_e2,
        w_rel, w_root, w_l1, w_l2, w_l3, b_pred, out,
        N, nbCnt, nbEnc, nbPack, nbRnd);

    int nblk = (N + 1023) / 1024;
    scan_a<<<nblk, 1024>>>(N);
    scan_b<<<1, 1024>>>(nblk);
    scan_c<<<nblk, 1024>>>(N);

    fill_kernel<<<(E + 1023) / 1024, 256>>>(eidx, E);
    gather_kernel<<<(N * 32 + 255) / 256, 256>>>(N);

    dim3 ggrid((N + 127) / 128, 2);
    gemm_f16<0><<<ggrid, 256, SMEM>>>(xc, w1, b_rel, h0, N, 80, nullptr, nullptr);
    gemm_f16<0><<<ggrid, 256, SMEM>>>(h0, wl, b_l1, h1, N, 256, nullptr, nullptr);
    gemm_f16<0><<<ggrid, 256, SMEM>>>(h1, wl + 65536, b_l2, h0, N, 256, nullptr, nullptr);
    gemm_f16<1><<<ggrid, 256, SMEM>>>(h0, wl + 2 * 65536, b_l3, nullptr, N, 256, w_pred, out);
}

// round 15
// speedup vs baseline: 1.4633x; 1.1241x over previous
#include <cuda_runtime.h>
#include <cuda_fp16.h>
#include <cstdint>

#define NEG_SLOPE 0.1f
__device__ __forceinline__ float lrelu(float v) { return v >= 0.f ? v : NEG_SLOPE * v; }

// ---------------- static scratch ----------------
#define MAXN 50176
#define MAXE 5000000
__device__ __align__(16) __half g_xc[MAXN * 80];     // [N,80] half: 0..39 agg, 40..79 x
__device__ __align__(16) __half g_w1cat[256 * 80];   // [256,80] = [w_rel|w_root] half
__device__ __align__(16) __half g_wl[3 * 256 * 256]; // w_l1,w_l2,w_l3 half
__device__ int g_cnt[MAXN];
__device__ int g_off[MAXN + 1];
__device__ int g_cur[MAXN];
__device__ int g_esrc[MAXE];
__device__ int g_bsum[64];
__device__ int g_bbase[64];

// per-block int64-vs-int32 detection for edge_index (values < 2^31 -> odd words all 0)
__device__ __forceinline__ int block_is64(const unsigned* p, long long nwords) {
    int t = threadIdx.x;
    int odd = 0;
    if (t < 256 && (2 * t + 1) < nwords) odd = (p[2 * t + 1] != 0u);
    return !__syncthreads_or(odd);
}

// ================= fused front: count | encoder | pack | out_init =================
__global__ void fused_front(const void* __restrict__ eidx, int E,
                            const float* __restrict__ pose, const float* __restrict__ views,
                            const float* __restrict__ w_e1, const float* __restrict__ b_e1,
                            const float* __restrict__ w_e2, const float* __restrict__ b_e2,
                            const float* __restrict__ w_rel, const float* __restrict__ w_root,
                            const float* __restrict__ w_l1, const float* __restrict__ w_l2,
                            const float* __restrict__ w_l3,
                            const float* __restrict__ b_pred, float* __restrict__ out,
                            int N, int nbCnt, int nbEnc, int nbPack, int nbRnd) {
    int bx = blockIdx.x;
    int t = threadIdx.x;

    if (bx < nbCnt) {
        int is64 = block_is64((const unsigned*)eidx, 2LL * E * 2);
        int base = bx * 1024;
#pragma unroll
        for (int j = 0; j < 4; j++) {
            int e = base + t + j * 256;
            if (e < E) {
                int dst;
                if (is64) dst = (int)((const long long*)eidx)[(size_t)E + e];
                else      dst = ((const int*)eidx)[E + e];
                atomicAdd(&g_cnt[dst], 1);
            }
        }
        return;
    }
    bx -= nbCnt;

    if (bx < nbEnc) {
        __shared__ float sw1[81], sb1[9], sw2[27], sb2;
        if (t < 81) sw1[t] = w_e1[t];
        if (t < 9)  sb1[t] = b_e1[t];
        if (t >= 96 && t < 123) sw2[t - 96] = w_e2[t - 96];
        if (t == 127) sb2 = b_e2[0];
        __syncthreads();

        int n = bx * 256 + t;
        if (n >= N) return;

        __half* xo = g_xc + (size_t)n * 80 + 40;
        xo[0] = __float2half_rn(pose[n * 3 + 0]);
        xo[1] = __float2half_rn(pose[n * 3 + 1]);
        xo[2] = __float2half_rn(pose[n * 3 + 2]);

        const float* vin = views + (size_t)n * 453;

        float cur[9];
        {
            float in[3][3];
#pragma unroll
            for (int ci = 0; ci < 3; ci++)
#pragma unroll
                for (int k = 0; k < 3; k++) in[ci][k] = vin[ci * 151 + k];
#pragma unroll
            for (int c1 = 0; c1 < 9; c1++) {
                float a = sb1[c1];
#pragma unroll
                for (int ci = 0; ci < 3; ci++)
#pragma unroll
                    for (int k = 0; k < 3; k++) a += sw1[c1 * 9 + ci * 3 + k] * in[ci][k];
                cur[c1] = lrelu(a);
            }
        }
        for (int tt = 0; tt < 37; tt++) {
            float b9[9], c9[9];
#pragma unroll
            for (int which = 0; which < 2; which++) {
                int pos = 2 * tt + 1 + which;
                float in[3][3];
#pragma unroll
                for (int ci = 0; ci < 3; ci++)
#pragma unroll
                    for (int k = 0; k < 3; k++) in[ci][k] = vin[ci * 151 + 2 * pos + k];
                float* dst = which == 0 ? b9 : c9;
#pragma unroll
                for (int c1 = 0; c1 < 9; c1++) {
                    float a = sb1[c1];
#pragma unroll
                    for (int ci = 0; ci < 3; ci++)
#pragma unroll
                        for (int k = 0; k < 3; k++) a += sw1[c1 * 9 + ci * 3 + k] * in[ci][k];
                    dst[c1] = lrelu(a);
                }
            }
            float acc = sb2;
#pragma unroll
            for (int c1 = 0; c1 < 9; c1++)
                acc += cur[c1] * sw2[c1 * 3 + 0] + b9[c1] * sw2[c1 * 3 + 1] + c9[c1] * sw2[c1 * 3 + 2];
            xo[3 + tt] = __float2half_rn(lrelu(acc));
#pragma unroll
            for (int c1 = 0; c1 < 9; c1++) cur[c1] = c9[c1];
        }
        return;
    }
    bx -= nbEnc;

    if (bx < nbPack) {
        int i = bx * 256 + t;
        if (i < 256 * 80) {
            int n = i / 80, j = i % 80;
            g_w1cat[i] = __float2half_rn((j < 40) ? w_rel[n * 40 + j] : w_root[n * 40 + j - 40]);
        }
        return;
    }
    bx -= nbPack;

    if (bx < nbRnd) {
        int i = bx * 256 + t;
        if (i < 3 * 65536) {
            int which = i >> 16;
            const float* w = which == 0 ? w_l1 : (which == 1 ? w_l2 : w_l3);
            g_wl[i] = __float2half_rn(w[i & 65535]);
        }
        return;
    }
    bx -= nbRnd;

    {
        int i = bx * 256 + t;
        if (i < N) out[i] = b_pred[0];
    }
}

// ================= scan (3 kernels) =================
__device__ __forceinline__ int block_incl_scan(int v) {
    __shared__ int ws[32];
    int lane = threadIdx.x & 31, wid = threadIdx.x >> 5;
    int x = v;
#pragma unroll
    for (int o = 1; o < 32; o <<= 1) {
        int y = __shfl_up_sync(0xffffffffu, x, o);
        if (lane >= o) x += y;
    }
    if (lane == 31) ws[wid] = x;
    __syncthreads();
    if (wid == 0) {
        int s = ws[lane];
#pragma unroll
        for (int o = 1; o < 32; o <<= 1) {
            int y = __shfl_up_sync(0xffffffffu, s, o);
            if (lane >= o) s += y;
        }
        ws[lane] = s;
    }
    __syncthreads();
    int base = (wid > 0) ? ws[wid - 1] : 0;
    return base + x;
}

__global__ void scan_a(int N) {
    int i = blockIdx.x * 1024 + threadIdx.x;
    int v = (i < N) ? g_cnt[i] : 0;
    int incl = block_incl_scan(v);
    if (threadIdx.x == 1023) g_bsum[blockIdx.x] = incl;
}
__global__ void scan_b(int nblk) {
    int t = threadIdx.x;
    int v = (t < nblk) ? g_bsum[t] : 0;
    int incl = block_incl_scan(v);
    if (t < nblk) g_bbase[t] = incl - v;
}
__global__ void scan_c(int N) {
    int b = blockIdx.x;
    int i = b * 1024 + threadIdx.x;
    int v = (i < N) ? g_cnt[i] : 0;
    int incl = block_incl_scan(v);
    int excl = g_bbase[b] + incl - v;
    if (i < N) { g_off[i] = excl; g_cur[i] = excl; }
    if (i == N - 1) g_off[N] = excl + v;
}

// ================= fill =================
__global__ void fill_kernel(const void* __restrict__ eidx, int E) {
    int is64 = block_is64((const unsigned*)eidx, 2LL * E * 2);
    int base = blockIdx.x * 1024;
    int t = threadIdx.x;
#pragma unroll
    for (int j = 0; j < 4; j++) {
        int e = base + t + j * 256;
        if (e < E) {
            int src, dst;
            if (is64) {
                const long long* p = (const long long*)eidx;
                src = (int)p[e];
                dst = (int)p[(size_t)E + e];
            } else {
                const int* p = (const int*)eidx;
                src = p[e];
                dst = p[E + e];
            }
            int pos = atomicAdd(&g_cur[dst], 1);
            g_esrc[pos] = src;
        }
    }
}

// ===== gather: warp per node; lanes 0..19 each own one half2 column of x-row =====
__global__ void gather_kernel(int N) {
    int w = (blockIdx.x * blockDim.x + threadIdx.x) >> 5;
    int lane = threadIdx.x & 31;
    if (w >= N || lane >= 20) return;
    int beg = g_off[w], end = g_off[w + 1];

    float ax = 0.f, ay = 0.f;
    const __half2* xb = (const __half2*)g_xc;  // row s: half2 index s*40 + 20 + lane

    int e = beg;
    for (; e + 3 < end; e += 4) {
        int s0 = g_esrc[e], s1 = g_esrc[e + 1], s2 = g_esrc[e + 2], s3 = g_esrc[e + 3];
        __half2 v0 = xb[(size_t)s0 * 40 + 20 + lane];
        __half2 v1 = xb[(size_t)s1 * 40 + 20 + lane];
        __half2 v2 = xb[(size_t)s2 * 40 + 20 + lane];
        __half2 v3 = xb[(size_t)s3 * 40 + 20 + lane];
        float2 f0 = __half22float2(v0);
        float2 f1 = __half22float2(v1);
        float2 f2 = __half22float2(v2);
        float2 f3 = __half22float2(v3);
        ax += (f0.x + f1.x) + (f2.x + f3.x);
        ay += (f0.y + f1.y) + (f2.y + f3.y);
    }
    for (; e < end; e++) {
        float2 f = __half22float2(xb[(size_t)g_esrc[e] * 40 + 20 + lane]);
        ax += f.x;
        ay += f.y;
    }
    ((__half2*)(g_xc + (size_t)w * 80))[lane] = __floats2half2_rn(ax, ay);
}

// ================= fused MLP: per-block 128 rows through all 4 layers =================
// 512 threads = 16 warps (4x4). Warp tile 32x64. h ping-pong in SMEM (2x64KB).
// SMEM word layout: H0 @0 (128x128w), H1 @16384, stages @32768:
//   layer1: stage s in {0,1}: A @32768+s*12288 (128x32w), B @+4096 (256x32w)
//   mid:    stage s in {0,1,2}: B @32768+s*8192 (256x32w)
// Swizzle everywhere: word col ^ ((row&7)<<2).
__device__ __forceinline__ void mma_f16(float c[4], const uint32_t a[4], const uint32_t b[2]) {
    asm volatile(
        "mma.sync.aligned.m16n8k16.row.col.f32.f16.f16.f32 "
        "{%0,%1,%2,%3}, {%4,%5,%6,%7}, {%8,%9}, {%0,%1,%2,%3};\n"
        : "+f"(c[0]), "+f"(c[1]), "+f"(c[2]), "+f"(c[3])
        : "r"(a[0]), "r"(a[1]), "r"(a[2]), "r"(a[3]), "r"(b[0]), "r"(b[1]));
}
__device__ __forceinline__ void cpasync16(uint32_t saddr, const void* g, int sz) {
    asm volatile("cp.async.cg.shared.global [%0], [%1], 16, %2;"
                 :: "r"(saddr), "l"(g), "r"(sz));
}

#define H0W 0
#define H1W 16384
#define STGW 32768
#define MLP_SMEM ((STGW + 3 * 8192 + 2) * 4 > (STGW + 2 * 12288) * 4 ? (STGW + 2 * 12288) * 4 : 0)
// stages max(3*8192, 2*12288) = 24576 words -> total 57344 words = 229376 B
#define MLP_SMEM_BYTES (57344 * 4)

__global__ __launch_bounds__(512, 1)
void mlp_fused(const __half* __restrict__ xc, const __half* __restrict__ w1,
               const __half* __restrict__ wl,
               const float* __restrict__ b_rel, const float* __restrict__ b_l1,
               const float* __restrict__ b_l2, const float* __restrict__ b_l3,
               const float* __restrict__ w_pred, const float* __restrict__ b_pred,
               float* __restrict__ out, int M) {
    extern __shared__ uint32_t sm[];
    uint32_t sbase = (uint32_t)__cvta_generic_to_shared(sm);
    __shared__ float wps[256];

    int tid = threadIdx.x;
    int m0 = blockIdx.x * 128;
    int wid = tid >> 5, lane = tid & 31;
    int wm = wid >> 2, wn = wid & 3;
    int g = lane >> 2, t = lane & 3;
    int xg = g << 2;

    if (tid < 256) wps[tid] = w_pred[tid];

    float c[2][8][4];

    // ---------------- layer 1: A = xc (K=80), B = w1 ----------------
    {
#pragma unroll
        for (int i = 0; i < 2; i++)
#pragma unroll
            for (int j = 0; j < 8; j++)
#pragma unroll
                for (int r = 0; r < 4; r++) c[i][j][r] = 0.f;

        auto load1 = [&](int k0, int s) {
#pragma unroll
            for (int p = 0; p < 2; p++) {  // A: 128 rows x 8 blocks
                int lin = tid + p * 512;
                int r = lin >> 3, cq = lin & 7;
                int k = k0 + cq * 8;
                bool v = (k < 80) && (m0 + r < M);
                uint32_t so = sbase + ((STGW + s * 12288 + r * 32 + ((cq * 4) ^ ((r & 7) << 2))) << 2);
                cpasync16(so, v ? (const void*)(xc + (size_t)(m0 + r) * 80 + k) : (const void*)xc,
                          v ? 16 : 0);
            }
#pragma unroll
            for (int p = 0; p < 4; p++) {  // B: 256 rows x 8 blocks
                int lin = tid + p * 512;
                int r = lin >> 3, cq = lin & 7;
                int k = k0 + cq * 8;
                bool v = (k < 80);
                uint32_t so = sbase + ((STGW + s * 12288 + 4096 + r * 32 + ((cq * 4) ^ ((r & 7) << 2))) << 2);
                cpasync16(so, v ? (const void*)(w1 + (size_t)r * 80 + k) : (const void*)w1,
                          v ? 16 : 0);
            }
            asm volatile("cp.async.commit_group;");
        };
        load1(0, 0);
        load1(64, 1);

        for (int i = 0; i < 2; i++) {
            if (i == 0) asm volatile("cp.async.wait_group 1;");
            else        asm volatile("cp.async.wait_group 0;");
            __syncthreads();
            const uint32_t* As = sm + STGW + i * 12288;
            const uint32_t* Bs = As + 4096;
            int nsteps = (i == 0) ? 4 : 1;
            for (int j = 0; j < nsteps; j++) {
                int c0 = (j * 8 + t) ^ xg;
                int c1 = (j * 8 + t + 4) ^ xg;
                uint32_t a[2][4], b[8][2];
#pragma unroll
                for (int mt = 0; mt < 2; mt++) {
                    int m = wm * 32 + mt * 16 + g;
                    a[mt][0] = As[m * 32 + c0];
                    a[mt][1] = As[(m + 8) * 32 + c0];
                    a[mt][2] = As[m * 32 + c1];
                    a[mt][3] = As[(m + 8) * 32 + c1];
                }
#pragma unroll
                for (int nt = 0; nt < 8; nt++) {
                    int n = wn * 64 + nt * 8 + g;
                    b[nt][0] = Bs[n * 32 + c0];
                    b[nt][1] = Bs[n * 32 + c1];
                }
#pragma unroll
                for (int mt = 0; mt < 2; mt++)
#pragma unroll
                    for (int nt = 0; nt < 8; nt++) mma_f16(c[mt][nt], a[mt], b[nt]);
            }
            __syncthreads();
        }
        // epilogue -> H0
#pragma unroll
        for (int mt = 0; mt < 2; mt++) {
            int row = wm * 32 + mt * 16 + g;
            int xr = (row & 7) << 2;
#pragma unroll
            for (int nt = 0; nt < 8; nt++) {
                int colw = wn * 32 + nt * 4 + t;
                float bx = b_rel[2 * colw], by = b_rel[2 * colw + 1];
                *(__half2*)&sm[H0W + row * 128 + (colw ^ xr)] =
                    __floats2half2_rn(lrelu(c[mt][nt][0] + bx), lrelu(c[mt][nt][1] + by));
                *(__half2*)&sm[H0W + (row + 8) * 128 + (colw ^ xr)] =
                    __floats2half2_rn(lrelu(c[mt][nt][2] + bx), lrelu(c[mt][nt][3] + by));
            }
        }
        __syncthreads();
    }

    // ---------------- mid layers: A = h_in (smem), B = weights ----------------
    auto midlayer = [&](const __half* B, const float* bias, int hinw, int houtw) {
#pragma unroll
        for (int i = 0; i < 2; i++)
#pragma unroll
            for (int j = 0; j < 8; j++)
#pragma unroll
                for (int r = 0; r < 4; r++) c[i][j][r] = 0.f;

        auto loadB = [&](int k0, int s) {
#pragma unroll
            for (int p = 0; p < 4; p++) {
                int lin = tid + p * 512;
                int r = lin >> 3, cq = lin & 7;
                int k = k0 + cq * 8;
                uint32_t so = sbase + ((STGW + s * 8192 + r * 32 + ((cq * 4) ^ ((r & 7) << 2))) << 2);
                cpasync16(so, (const void*)(B + (size_t)r * 256 + k), 16);
            }
            asm volatile("cp.async.commit_group;");
        };
        loadB(0, 0);
        loadB(64, 1);

        for (int i = 0; i < 4; i++) {
            if (i + 2 < 4) {
                loadB((i + 2) * 64, (i + 2) % 3);
                asm volatile("cp.async.wait_group 2;");
            } else if (i + 1 < 4) {
                asm volatile("cp.async.wait_group 1;");
            } else {
                asm volatile("cp.async.wait_group 0;");
            }
            __syncthreads();
            const uint32_t* Bs = sm + STGW + (i % 3) * 8192;
            const uint32_t* Hin = sm + hinw;
#pragma unroll
            for (int j = 0; j < 4; j++) {
                int wb = i * 32 + j * 8;            // word col in h row (0..127)
                int hc0 = (wb + t) ^ xg;
                int hc1 = (wb + t + 4) ^ xg;
                int bc0 = (j * 8 + t) ^ xg;         // word col in B stage (0..31)
                int bc1 = (j * 8 + t + 4) ^ xg;
                uint32_t a[2][4], b[8][2];
#pragma unroll
                for (int mt = 0; mt < 2; mt++) {
                    int m = wm * 32 + mt * 16 + g;
                    a[mt][0] = Hin[m * 128 + hc0];
                    a[mt][1] = Hin[(m + 8) * 128 + hc0];
                    a[mt][2] = Hin[m * 128 + hc1];
                    a[mt][3] = Hin[(m + 8) * 128 + hc1];
                }
#pragma unroll
                for (int nt = 0; nt < 8; nt++) {
                    int n = wn * 64 + nt * 8 + g;
                    b[nt][0] = Bs[n * 32 + bc0];
                    b[nt][1] = Bs[n * 32 + bc1];
                }
#pragma unroll
                for (int mt = 0; mt < 2; mt++)
#pragma unroll
                    for (int nt = 0; nt < 8; nt++) mma_f16(c[mt][nt], a[mt], b[nt]);
            }
            __syncthreads();
        }
        // epilogue -> hout
#pragma unroll
        for (int mt = 0; mt < 2; mt++) {
            int row = wm * 32 + mt * 16 + g;
            int xr = (row & 7) << 2;
#pragma unroll
            for (int nt = 0; nt < 8; nt++) {
                int colw = wn * 32 + nt * 4 + t;
                float bx = bias[2 * colw], by = bias[2 * colw + 1];
                *(__half2*)&sm[houtw + row * 128 + (colw ^ xr)] =
                    __floats2half2_rn(lrelu(c[mt][nt][0] + bx), lrelu(c[mt][nt][1] + by));
                *(__half2*)&sm[houtw + (row + 8) * 128 + (colw ^ xr)] =
                    __floats2half2_rn(lrelu(c[mt][nt][2] + bx), lrelu(c[mt][nt][3] + by));
            }
        }
        __syncthreads();
    };

    midlayer(wl, b_l1, H0W, H1W);                 // l1': H0 -> H1
    midlayer(wl + 65536, b_l2, H1W, H0W);         // l2 : H1 -> H0
    midlayer(wl + 2 * 65536, b_l3, H0W, H1W);     // l3 : H0 -> H1

    // ---------------- pred: out[m] = H1[m,:] . w_pred + b_pred ----------------
    {
        int row = tid >> 2;       // 0..127
        int q = tid & 3;          // 32 word-cols each
        int xr = (row & 7) << 2;
        float d = 0.f;
#pragma unroll
        for (int w = 0; w < 32; w++) {
            int colw = q * 32 + w;
            float2 f = __half22float2(*(const __half2*)&sm[H1W + row * 128 + (colw ^ xr)]);
            d += f.x * wps[2 * colw] + f.y * wps[2 * colw + 1];
        }
        d += __shfl_xor_sync(0xffffffffu, d, 1);
        d += __shfl_xor_sync(0xffffffffu, d, 2);
        if (q == 0 && m0 + row < M) out[m0 + row] = d + b_pred[0];
    }
}

extern "C" void kernel_launch(void* const* d_in, const int* in_sizes, int n_in,
                              void* d_out, int out_size) {
    const float* pose   = (const float*)d_in[0];
    const float* views  = (const float*)d_in[1];
    const void*  eidx   = d_in[2];
    const float* w_e1   = (const float*)d_in[3];
    const float* b_e1   = (const float*)d_in[4];
    const float* w_e2   = (const float*)d_in[5];
    const float* b_e2   = (const float*)d_in[6];
    const float* w_rel  = (const float*)d_in[7];
    const float* b_rel  = (const float*)d_in[8];
    const float* w_root = (const float*)d_in[9];
    const float* w_l1   = (const float*)d_in[10];
    const float* b_l1   = (const float*)d_in[11];
    const float* w_l2   = (const float*)d_in[12];
    const float* b_l2   = (const float*)d_in[13];
    const float* w_l3   = (const float*)d_in[14];
    const float* b_l3   = (const float*)d_in[15];
    const float* w_pred = (const float*)d_in[16];
    const float* b_pred = (const float*)d_in[17];
    float* out = (float*)d_out;

    int N = in_sizes[0] / 3;
    int E = in_sizes[2] / 2;

    __half *xc, *w1, *wl;
    cudaGetSymbolAddress((void**)&xc, g_xc);
    cudaGetSymbolAddress((void**)&w1, g_w1cat);
    cudaGetSymbolAddress((void**)&wl, g_wl);
    int* cnt;
    cudaGetSymbolAddress((void**)&cnt, g_cnt);

    cudaFuncSetAttribute(mlp_fused, cudaFuncAttributeMaxDynamicSharedMemorySize,
                         MLP_SMEM_BYTES);

    cudaMemsetAsync(cnt, 0, (size_t)N * sizeof(int));

    int nbCnt = (E + 1023) / 1024;
    int nbEnc = (N + 255) / 256;
    int nbPack = (256 * 80 + 255) / 256;
    int nbRnd = (3 * 65536 + 255) / 256;
    int nbOut = (N + 255) / 256;
    fused_front<<<nbCnt + nbEnc + nbPack + nbRnd + nbOut, 256>>>(
        eidx, E, pose, views, w_e1, b_e1, w_e2, b_e2,
        w_rel, w_root, w_l1, w_l2, w_l3, b_pred, out,
        N, nbCnt, nbEnc, nbPack, nbRnd);

    int nblk = (N + 1023) / 1024;
    scan_a<<<nblk, 1024>>>(N);
    scan_b<<<1, 1024>>>(nblk);
    scan_c<<<nblk, 1024>>>(N);

    fill_kernel<<<(E + 1023) / 1024, 256>>>(eidx, E);
    gather_kernel<<<(N * 32 + 255) / 256, 256>>>(N);

    mlp_fused<<<(N + 127) / 128, 512, MLP_SMEM_BYTES>>>(
        xc, w1, wl, b_rel, b_l1, b_l2, b_l3, w_pred, b_pred, out, N);
}